// round 2
// baseline (speedup 1.0000x reference)
#include <cuda_runtime.h>
#include <cstdint>

#define T_DATA 50000
#define E_NO   1000
#define I_NO   200
#define SUB_NO 20
#define H_NO   16
#define T_NO   200
#define COS_NO 20

// ---------------- persistent scratch (device globals; no allocation) --------
__device__ float g_Sg[2 * SUB_NO][T_DATA];                 // channel-major grouped signals (8 MB)
__device__ float g_kernT[SUB_NO][2][T_NO][H_NO];           // causal kernels, h-fastest (1 MB)
__device__ float g_partial[SUB_NO][T_DATA];                // per-subunit root partials (4 MB)

__device__ __forceinline__ float lrelu(float x) {
    return x >= 0.0f ? x : 0.01f * x;
}

// ---------------------------------------------------------------------------
// Kernel 1: build raised-cosine basis, synthesize temporal kernels.
// Writes g_kernT[s][c][k][h] (causal, unflipped) and, if requested, the
// flipped conv_kern into the output buffer at d_out + T_DATA.
// ---------------------------------------------------------------------------
__global__ void prep_kern(const float* __restrict__ W_conv,
                          float* __restrict__ out_kern, int write_out)
{
    __shared__ float basis[COS_NO][T_NO];
    const int s = blockIdx.x;
    const float PI = 3.14159265358979323846f;

    for (int idx = threadIdx.x; idx < COS_NO * T_NO; idx += blockDim.x) {
        int b = idx / T_NO, t = idx % T_NO;
        float phi = 1.5707963267948966f * (float)b;
        float raw = 5.0f * logf((float)t + 1.0f);
        float v = 0.5f * cosf(raw - phi) + 0.5f;
        basis[b][t] = (raw >= phi - PI && raw <= phi + PI) ? v : 0.0f;
    }
    __syncthreads();

    for (int idx = threadIdx.x; idx < H_NO * 2 * T_NO; idx += blockDim.x) {
        int h = idx / (2 * T_NO);
        int c = (idx / T_NO) & 1;
        int k = idx % T_NO;
        int o = s * H_NO + h;
        const float* w = W_conv + (o * 2 + c) * COS_NO;
        float acc = 0.0f;
#pragma unroll
        for (int b = 0; b < COS_NO; b++) acc = fmaf(w[b], basis[b][k], acc);
        g_kernT[s][c][k][h] = acc;
        if (write_out)
            out_kern[(o * 2 + c) * T_NO + (T_NO - 1 - k)] = acc;
    }
}

// ---------------------------------------------------------------------------
// Kernel 2: synapse grouping GEMM.
//   g_Sg[2s  ][t] = sum_e S_e[t,e] * C_syn_e[s,e]
//   g_Sg[2s+1][t] = sum_i S_i[t,i] * C_syn_i[s,i]
// Block: 256 threads, 128-row time tile, K-chunks of 40. Each thread owns
// 2 rows x 5 columns of accumulators; float4 smem reads.
// ---------------------------------------------------------------------------
#define GM_ROWS 128
#define GM_KC   40
#define GM_PAD  44   // row stride (floats): 16B aligned, conflict-free

__global__ __launch_bounds__(256) void group_gemm(
    const float* __restrict__ S_e, const float* __restrict__ S_i,
    const float* __restrict__ Ce,  const float* __restrict__ Ci)
{
    __shared__ float sS[GM_ROWS][GM_PAD];
    __shared__ float sC[SUB_NO][GM_PAD];

    const int t0 = blockIdx.x * GM_ROWS;
    const int tid = threadIdx.x;
    const int w = tid >> 5, lane = tid & 31;
    const int cg = w >> 1;           // column group 0..3 -> cols [5*cg, 5*cg+5)
    const int rh = w & 1;
    const int r0 = rh * 64 + lane;   // rows r0 and r0+32

    for (int ph = 0; ph < 2; ph++) {
        const float* S = ph ? S_i : S_e;
        const float* C = ph ? Ci : Ce;
        const int K = ph ? I_NO : E_NO;

        float acc0[5] = {0.f, 0.f, 0.f, 0.f, 0.f};
        float acc1[5] = {0.f, 0.f, 0.f, 0.f, 0.f};

        for (int kc = 0; kc < K; kc += GM_KC) {
            // load 128 x 40 S tile (each thread: 5 float4)
            {
                int r = tid >> 1, half = tid & 1;
                int row = t0 + r;
#pragma unroll
                for (int j = 0; j < 5; j++) {
                    int col = kc + half * 20 + j * 4;
                    float4 v = make_float4(0.f, 0.f, 0.f, 0.f);
                    if (row < T_DATA)
                        v = *(const float4*)&S[(size_t)row * K + col];
                    *(float4*)&sS[r][half * 20 + j * 4] = v;
                }
            }
            // load 20 x 40 C tile
            if (tid < 200) {
                int col = tid / 10, seg = tid % 10;
                *(float4*)&sC[col][seg * 4] =
                    *(const float4*)&C[col * K + kc + seg * 4];
            }
            __syncthreads();

#pragma unroll
            for (int k4 = 0; k4 < GM_KC; k4 += 4) {
                float4 a0 = *(float4*)&sS[r0][k4];
                float4 a1 = *(float4*)&sS[r0 + 32][k4];
#pragma unroll
                for (int j = 0; j < 5; j++) {
                    float4 b = *(float4*)&sC[cg * 5 + j][k4];
                    acc0[j] = fmaf(a0.x, b.x, fmaf(a0.y, b.y,
                              fmaf(a0.z, b.z, fmaf(a0.w, b.w, acc0[j]))));
                    acc1[j] = fmaf(a1.x, b.x, fmaf(a1.y, b.y,
                              fmaf(a1.z, b.z, fmaf(a1.w, b.w, acc1[j]))));
                }
            }
            __syncthreads();
        }
#pragma unroll
        for (int j = 0; j < 5; j++) {
            int ch = 2 * (cg * 5 + j) + ph;
            if (t0 + r0 < T_DATA)      g_Sg[ch][t0 + r0]      = acc0[j];
            if (t0 + r0 + 32 < T_DATA) g_Sg[ch][t0 + r0 + 32] = acc1[j];
        }
    }
}

// ---------------------------------------------------------------------------
// Kernel 3: fused causal conv (K=400 taps) + leaky + 2-layer MLP + root dot.
// Grid: (time tiles, SUB_NO). 128 threads, 512-t tile, 4 t per thread,
// all 16 h in registers.
// ---------------------------------------------------------------------------
#define CT       512
#define CTHREADS 128

__global__ __launch_bounds__(CTHREADS) void conv_mlp(
    const float* __restrict__ ff_w,  const float* __restrict__ ff_b,
    const float* __restrict__ ff2_w, const float* __restrict__ ff2_b,
    const float* __restrict__ root_w)
{
    __shared__ float kern[2][T_NO][H_NO];          // 25.6 KB
    __shared__ float win[2][CT + T_NO];            // sliding window
    __shared__ float W1[H_NO][H_NO], W2[H_NO][H_NO];
    __shared__ float B1[H_NO], B2[H_NO], RW[H_NO];

    const int s  = blockIdx.y;
    const int t0 = blockIdx.x * CT;
    const int tid = threadIdx.x;

    // fill kernel slice (contiguous, float4)
    {
        const float4* src = (const float4*)&g_kernT[s][0][0][0];
        float4* dst = (float4*)&kern[0][0][0];
        for (int i = tid; i < (2 * T_NO * H_NO) / 4; i += CTHREADS)
            dst[i] = src[i];
    }
    // fill signal window: win[c][j] = Sg[2s+c][t0 + j - 199] (0 if OOB)
    for (int c = 0; c < 2; c++) {
        const float* src = g_Sg[2 * s + c];
        for (int j = tid; j < CT + T_NO - 1; j += CTHREADS) {
            int t = t0 + j - (T_NO - 1);
            win[c][j] = (t >= 0 && t < T_DATA) ? src[t] : 0.0f;
        }
    }
    // MLP weights
    for (int i = tid; i < H_NO * H_NO; i += CTHREADS) {
        W1[i >> 4][i & 15] = ff_w[s * H_NO * H_NO + i];
        W2[i >> 4][i & 15] = ff2_w[s * H_NO * H_NO + i];
    }
    if (tid < H_NO) {
        B1[tid] = ff_b[s * H_NO + tid];
        B2[tid] = ff2_b[s * H_NO + tid];
        RW[tid] = root_w[s * H_NO + tid];
    }
    __syncthreads();

    float acc[4][H_NO];
#pragma unroll
    for (int q = 0; q < 4; q++)
#pragma unroll
        for (int h = 0; h < H_NO; h++) acc[q][h] = 0.0f;

    for (int c = 0; c < 2; c++) {
        const float* wp = &win[c][tid + (T_NO - 1)];
        const float4* kp = (const float4*)&kern[c][0][0];
#pragma unroll 4
        for (int k = 0; k < T_NO; k++) {
            float4 k0 = kp[k * 4 + 0];
            float4 k1 = kp[k * 4 + 1];
            float4 k2 = kp[k * 4 + 2];
            float4 k3 = kp[k * 4 + 3];
            float sv[4];
#pragma unroll
            for (int q = 0; q < 4; q++) sv[q] = wp[q * CTHREADS - k];
#pragma unroll
            for (int q = 0; q < 4; q++) {
                float v = sv[q];
                acc[q][0]  = fmaf(v, k0.x, acc[q][0]);
                acc[q][1]  = fmaf(v, k0.y, acc[q][1]);
                acc[q][2]  = fmaf(v, k0.z, acc[q][2]);
                acc[q][3]  = fmaf(v, k0.w, acc[q][3]);
                acc[q][4]  = fmaf(v, k1.x, acc[q][4]);
                acc[q][5]  = fmaf(v, k1.y, acc[q][5]);
                acc[q][6]  = fmaf(v, k1.z, acc[q][6]);
                acc[q][7]  = fmaf(v, k1.w, acc[q][7]);
                acc[q][8]  = fmaf(v, k2.x, acc[q][8]);
                acc[q][9]  = fmaf(v, k2.y, acc[q][9]);
                acc[q][10] = fmaf(v, k2.z, acc[q][10]);
                acc[q][11] = fmaf(v, k2.w, acc[q][11]);
                acc[q][12] = fmaf(v, k3.x, acc[q][12]);
                acc[q][13] = fmaf(v, k3.y, acc[q][13]);
                acc[q][14] = fmaf(v, k3.z, acc[q][14]);
                acc[q][15] = fmaf(v, k3.w, acc[q][15]);
            }
        }
    }

    // MLP + root partial, one t at a time (keeps registers bounded)
#pragma unroll
    for (int q = 0; q < 4; q++) {
        int t = t0 + tid + q * CTHREADS;
        float x[H_NO], h1[H_NO];
#pragma unroll
        for (int h = 0; h < H_NO; h++) x[h] = lrelu(acc[q][h]);
#pragma unroll
        for (int o = 0; o < H_NO; o++) {
            float a = B1[o];
#pragma unroll
            for (int i = 0; i < H_NO; i++) a = fmaf(W1[o][i], x[i], a);
            h1[o] = lrelu(a);
        }
        float p = 0.0f;
#pragma unroll
        for (int o = 0; o < H_NO; o++) {
            float a = B2[o];
#pragma unroll
            for (int i = 0; i < H_NO; i++) a = fmaf(W2[o][i], h1[i], a);
            p = fmaf(lrelu(a), RW[o], p);
        }
        if (t < T_DATA) g_partial[s][t] = p;
    }
}

// ---------------------------------------------------------------------------
// Kernel 4: V[t] = sum_s partial[s][t] + root_b + V_o
// ---------------------------------------------------------------------------
__global__ void finalize(const float* __restrict__ root_b,
                         const float* __restrict__ V_o,
                         float* __restrict__ out)
{
    int t = blockIdx.x * 256 + threadIdx.x;
    if (t >= T_DATA) return;
    float sum = root_b[0] + V_o[0];
#pragma unroll
    for (int s = 0; s < SUB_NO; s++) sum += g_partial[s][t];
    out[t] = sum;
}

// ---------------------------------------------------------------------------
extern "C" void kernel_launch(void* const* d_in, const int* in_sizes, int n_in,
                              void* d_out, int out_size)
{
    const float* S_e    = (const float*)d_in[0];
    const float* S_i    = (const float*)d_in[1];
    const float* C_e    = (const float*)d_in[2];
    const float* C_i    = (const float*)d_in[3];
    const float* W_conv = (const float*)d_in[4];
    const float* ff_w   = (const float*)d_in[5];
    const float* ff_b   = (const float*)d_in[6];
    const float* ff2_w  = (const float*)d_in[7];
    const float* ff2_b  = (const float*)d_in[8];
    const float* root_w = (const float*)d_in[9];
    const float* root_b = (const float*)d_in[10];
    const float* V_o    = (const float*)d_in[11];
    (void)in_sizes; (void)n_in;

    float* out = (float*)d_out;
    const int kern_elems = SUB_NO * H_NO * 2 * T_NO;      // 128000
    int write_kern = (out_size >= T_DATA + kern_elems) ? 1 : 0;

    prep_kern<<<SUB_NO, 256>>>(W_conv, out + T_DATA, write_kern);

    group_gemm<<<(T_DATA + GM_ROWS - 1) / GM_ROWS, 256>>>(S_e, S_i, C_e, C_i);

    dim3 cgrid((T_DATA + CT - 1) / CT, SUB_NO);
    conv_mlp<<<cgrid, CTHREADS>>>(ff_w, ff_b, ff2_w, ff2_b, root_w);

    finalize<<<(T_DATA + 255) / 256, 256>>>(root_b, V_o, out);
}

// round 3
// speedup vs baseline: 1.2755x; 1.2755x over previous
#include <cuda_runtime.h>
#include <cstdint>

#define T_DATA 50000
#define E_NO   1000
#define I_NO   200
#define SUB_NO 20
#define H_NO   16
#define T_NO   200
#define COS_NO 20

// ---------------- persistent scratch (device globals; no allocation) --------
__device__ float g_Sg[2 * SUB_NO][T_DATA];                 // channel-major grouped signals (8 MB)
__device__ float g_kernT[SUB_NO][2][T_NO][H_NO];           // causal kernels, h-fastest (1 MB)
__device__ float g_partial[SUB_NO][T_DATA];                // per-subunit root partials (4 MB)

__device__ __forceinline__ float lrelu(float x) {
    return x >= 0.0f ? x : 0.01f * x;
}

// ---------------- packed f32x2 helpers (Blackwell) -------------------------
__device__ __forceinline__ unsigned long long f32x2_fma(
    unsigned long long a, unsigned long long b, unsigned long long c)
{
    unsigned long long d;
    asm("fma.rn.f32x2 %0, %1, %2, %3;" : "=l"(d) : "l"(a), "l"(b), "l"(c));
    return d;
}
__device__ __forceinline__ unsigned long long f32x2_bcast(float x)
{
    unsigned long long r;
    asm("mov.b64 %0, {%1, %1};" : "=l"(r) : "f"(x));
    return r;
}
__device__ __forceinline__ unsigned long long f32x2_pack(float lo, float hi)
{
    unsigned long long r;
    asm("mov.b64 %0, {%1, %2};" : "=l"(r) : "f"(lo), "f"(hi));
    return r;
}
__device__ __forceinline__ void f32x2_unpack(unsigned long long v, float& lo, float& hi)
{
    asm("mov.b64 {%0, %1}, %2;" : "=f"(lo), "=f"(hi) : "l"(v));
}

// ---------------------------------------------------------------------------
// Kernel 1: build raised-cosine basis, synthesize temporal kernels.
// ---------------------------------------------------------------------------
__global__ void prep_kern(const float* __restrict__ W_conv,
                          float* __restrict__ out_kern, int write_out)
{
    __shared__ float basis[COS_NO][T_NO];
    const int s = blockIdx.x;
    const float PI = 3.14159265358979323846f;

    for (int idx = threadIdx.x; idx < COS_NO * T_NO; idx += blockDim.x) {
        int b = idx / T_NO, t = idx % T_NO;
        float phi = 1.5707963267948966f * (float)b;
        float raw = 5.0f * logf((float)t + 1.0f);
        float v = 0.5f * cosf(raw - phi) + 0.5f;
        basis[b][t] = (raw >= phi - PI && raw <= phi + PI) ? v : 0.0f;
    }
    __syncthreads();

    for (int idx = threadIdx.x; idx < H_NO * 2 * T_NO; idx += blockDim.x) {
        int h = idx / (2 * T_NO);
        int c = (idx / T_NO) & 1;
        int k = idx % T_NO;
        int o = s * H_NO + h;
        const float* w = W_conv + (o * 2 + c) * COS_NO;
        float acc = 0.0f;
#pragma unroll
        for (int b = 0; b < COS_NO; b++) acc = fmaf(w[b], basis[b][k], acc);
        g_kernT[s][c][k][h] = acc;
        if (write_out)
            out_kern[(o * 2 + c) * T_NO + (T_NO - 1 - k)] = acc;
    }
}

// ---------------------------------------------------------------------------
// Kernel 2: synapse grouping GEMM (unchanged from R2 — next optimization target)
// ---------------------------------------------------------------------------
#define GM_ROWS 128
#define GM_KC   40
#define GM_PAD  44

__global__ __launch_bounds__(256) void group_gemm(
    const float* __restrict__ S_e, const float* __restrict__ S_i,
    const float* __restrict__ Ce,  const float* __restrict__ Ci)
{
    __shared__ float sS[GM_ROWS][GM_PAD];
    __shared__ float sC[SUB_NO][GM_PAD];

    const int t0 = blockIdx.x * GM_ROWS;
    const int tid = threadIdx.x;
    const int w = tid >> 5, lane = tid & 31;
    const int cg = w >> 1;
    const int rh = w & 1;
    const int r0 = rh * 64 + lane;

    for (int ph = 0; ph < 2; ph++) {
        const float* S = ph ? S_i : S_e;
        const float* C = ph ? Ci : Ce;
        const int K = ph ? I_NO : E_NO;

        float acc0[5] = {0.f, 0.f, 0.f, 0.f, 0.f};
        float acc1[5] = {0.f, 0.f, 0.f, 0.f, 0.f};

        for (int kc = 0; kc < K; kc += GM_KC) {
            {
                int r = tid >> 1, half = tid & 1;
                int row = t0 + r;
#pragma unroll
                for (int j = 0; j < 5; j++) {
                    int col = kc + half * 20 + j * 4;
                    float4 v = make_float4(0.f, 0.f, 0.f, 0.f);
                    if (row < T_DATA)
                        v = *(const float4*)&S[(size_t)row * K + col];
                    *(float4*)&sS[r][half * 20 + j * 4] = v;
                }
            }
            if (tid < 200) {
                int col = tid / 10, seg = tid % 10;
                *(float4*)&sC[col][seg * 4] =
                    *(const float4*)&C[col * K + kc + seg * 4];
            }
            __syncthreads();

#pragma unroll
            for (int k4 = 0; k4 < GM_KC; k4 += 4) {
                float4 a0 = *(float4*)&sS[r0][k4];
                float4 a1 = *(float4*)&sS[r0 + 32][k4];
#pragma unroll
                for (int j = 0; j < 5; j++) {
                    float4 b = *(float4*)&sC[cg * 5 + j][k4];
                    acc0[j] = fmaf(a0.x, b.x, fmaf(a0.y, b.y,
                              fmaf(a0.z, b.z, fmaf(a0.w, b.w, acc0[j]))));
                    acc1[j] = fmaf(a1.x, b.x, fmaf(a1.y, b.y,
                              fmaf(a1.z, b.z, fmaf(a1.w, b.w, acc1[j]))));
                }
            }
            __syncthreads();
        }
#pragma unroll
        for (int j = 0; j < 5; j++) {
            int ch = 2 * (cg * 5 + j) + ph;
            if (t0 + r0 < T_DATA)      g_Sg[ch][t0 + r0]      = acc0[j];
            if (t0 + r0 + 32 < T_DATA) g_Sg[ch][t0 + r0 + 32] = acc1[j];
        }
    }
}

// ---------------------------------------------------------------------------
// Kernel 3: fused causal conv + MLP, inner loops in packed f32x2.
// ---------------------------------------------------------------------------
#define CT       512
#define CTHREADS 128

__global__ __launch_bounds__(CTHREADS) void conv_mlp(
    const float* __restrict__ ff_w,  const float* __restrict__ ff_b,
    const float* __restrict__ ff2_w, const float* __restrict__ ff2_b,
    const float* __restrict__ root_w)
{
    __shared__ float kern[2][T_NO][H_NO];          // 25.6 KB, h-fastest
    __shared__ float win[2][CT + T_NO];
    __shared__ float W1[H_NO][H_NO], W2[H_NO][H_NO];
    __shared__ float B1[H_NO], B2[H_NO], RW[H_NO];

    const int s  = blockIdx.y;
    const int t0 = blockIdx.x * CT;
    const int tid = threadIdx.x;

    {
        const float4* src = (const float4*)&g_kernT[s][0][0][0];
        float4* dst = (float4*)&kern[0][0][0];
        for (int i = tid; i < (2 * T_NO * H_NO) / 4; i += CTHREADS)
            dst[i] = src[i];
    }
    for (int c = 0; c < 2; c++) {
        const float* src = g_Sg[2 * s + c];
        for (int j = tid; j < CT + T_NO - 1; j += CTHREADS) {
            int t = t0 + j - (T_NO - 1);
            win[c][j] = (t >= 0 && t < T_DATA) ? src[t] : 0.0f;
        }
    }
    for (int i = tid; i < H_NO * H_NO; i += CTHREADS) {
        W1[i >> 4][i & 15] = ff_w[s * H_NO * H_NO + i];
        W2[i >> 4][i & 15] = ff2_w[s * H_NO * H_NO + i];
    }
    if (tid < H_NO) {
        B1[tid] = ff_b[s * H_NO + tid];
        B2[tid] = ff2_b[s * H_NO + tid];
        RW[tid] = root_w[s * H_NO + tid];
    }
    __syncthreads();

    // packed accumulators: acc2[q][p] = {acc[q][2p], acc[q][2p+1]}
    unsigned long long acc2[4][8];
#pragma unroll
    for (int q = 0; q < 4; q++)
#pragma unroll
        for (int p = 0; p < 8; p++) acc2[q][p] = 0ULL;

    for (int c = 0; c < 2; c++) {
        const float* wp = &win[c][tid + (T_NO - 1)];
        const ulonglong2* kp = (const ulonglong2*)&kern[c][0][0];
#pragma unroll 4
        for (int k = 0; k < T_NO; k++) {
            ulonglong2 ka  = kp[k * 4 + 0];   // h0..3
            ulonglong2 kb  = kp[k * 4 + 1];   // h4..7
            ulonglong2 kc2 = kp[k * 4 + 2];   // h8..11
            ulonglong2 kd  = kp[k * 4 + 3];   // h12..15
            float sv[4];
#pragma unroll
            for (int q = 0; q < 4; q++) sv[q] = wp[q * CTHREADS - k];
#pragma unroll
            for (int q = 0; q < 4; q++) {
                unsigned long long vv = f32x2_bcast(sv[q]);
                acc2[q][0] = f32x2_fma(vv, ka.x,  acc2[q][0]);
                acc2[q][1] = f32x2_fma(vv, ka.y,  acc2[q][1]);
                acc2[q][2] = f32x2_fma(vv, kb.x,  acc2[q][2]);
                acc2[q][3] = f32x2_fma(vv, kb.y,  acc2[q][3]);
                acc2[q][4] = f32x2_fma(vv, kc2.x, acc2[q][4]);
                acc2[q][5] = f32x2_fma(vv, kc2.y, acc2[q][5]);
                acc2[q][6] = f32x2_fma(vv, kd.x,  acc2[q][6]);
                acc2[q][7] = f32x2_fma(vv, kd.y,  acc2[q][7]);
            }
        }
    }

    // MLP + root partial; layer dots in packed f32x2 (8 packs over i).
#pragma unroll
    for (int q = 0; q < 4; q++) {
        int t = t0 + tid + q * CTHREADS;
        float x[H_NO], h1[H_NO];
#pragma unroll
        for (int p = 0; p < 8; p++) {
            float lo, hi;
            f32x2_unpack(acc2[q][p], lo, hi);
            x[2 * p]     = lrelu(lo);
            x[2 * p + 1] = lrelu(hi);
        }
        unsigned long long xp[8];
#pragma unroll
        for (int p = 0; p < 8; p++) xp[p] = f32x2_pack(x[2 * p], x[2 * p + 1]);

#pragma unroll
        for (int o = 0; o < H_NO; o++) {
            const ulonglong2* wrow = (const ulonglong2*)&W1[o][0];
            ulonglong2 w0 = wrow[0], w1 = wrow[1], w2 = wrow[2], w3 = wrow[3];
            unsigned long long a2 = f32x2_fma(xp[0], w0.x, 0ULL);
            a2 = f32x2_fma(xp[1], w0.y, a2);
            a2 = f32x2_fma(xp[2], w1.x, a2);
            a2 = f32x2_fma(xp[3], w1.y, a2);
            a2 = f32x2_fma(xp[4], w2.x, a2);
            a2 = f32x2_fma(xp[5], w2.y, a2);
            a2 = f32x2_fma(xp[6], w3.x, a2);
            a2 = f32x2_fma(xp[7], w3.y, a2);
            float lo, hi;
            f32x2_unpack(a2, lo, hi);
            h1[o] = lrelu(B1[o] + lo + hi);
        }
        unsigned long long hp[8];
#pragma unroll
        for (int p = 0; p < 8; p++) hp[p] = f32x2_pack(h1[2 * p], h1[2 * p + 1]);

        float pacc = 0.0f;
#pragma unroll
        for (int o = 0; o < H_NO; o++) {
            const ulonglong2* wrow = (const ulonglong2*)&W2[o][0];
            ulonglong2 w0 = wrow[0], w1 = wrow[1], w2 = wrow[2], w3 = wrow[3];
            unsigned long long a2 = f32x2_fma(hp[0], w0.x, 0ULL);
            a2 = f32x2_fma(hp[1], w0.y, a2);
            a2 = f32x2_fma(hp[2], w1.x, a2);
            a2 = f32x2_fma(hp[3], w1.y, a2);
            a2 = f32x2_fma(hp[4], w2.x, a2);
            a2 = f32x2_fma(hp[5], w2.y, a2);
            a2 = f32x2_fma(hp[6], w3.x, a2);
            a2 = f32x2_fma(hp[7], w3.y, a2);
            float lo, hi;
            f32x2_unpack(a2, lo, hi);
            pacc = fmaf(lrelu(B2[o] + lo + hi), RW[o], pacc);
        }
        if (t < T_DATA) g_partial[s][t] = pacc;
    }
}

// ---------------------------------------------------------------------------
// Kernel 4: V[t] = sum_s partial[s][t] + root_b + V_o
// ---------------------------------------------------------------------------
__global__ void finalize(const float* __restrict__ root_b,
                         const float* __restrict__ V_o,
                         float* __restrict__ out)
{
    int t = blockIdx.x * 256 + threadIdx.x;
    if (t >= T_DATA) return;
    float sum = root_b[0] + V_o[0];
#pragma unroll
    for (int s = 0; s < SUB_NO; s++) sum += g_partial[s][t];
    out[t] = sum;
}

// ---------------------------------------------------------------------------
extern "C" void kernel_launch(void* const* d_in, const int* in_sizes, int n_in,
                              void* d_out, int out_size)
{
    const float* S_e    = (const float*)d_in[0];
    const float* S_i    = (const float*)d_in[1];
    const float* C_e    = (const float*)d_in[2];
    const float* C_i    = (const float*)d_in[3];
    const float* W_conv = (const float*)d_in[4];
    const float* ff_w   = (const float*)d_in[5];
    const float* ff_b   = (const float*)d_in[6];
    const float* ff2_w  = (const float*)d_in[7];
    const float* ff2_b  = (const float*)d_in[8];
    const float* root_w = (const float*)d_in[9];
    const float* root_b = (const float*)d_in[10];
    const float* V_o    = (const float*)d_in[11];
    (void)in_sizes; (void)n_in;

    float* out = (float*)d_out;
    const int kern_elems = SUB_NO * H_NO * 2 * T_NO;
    int write_kern = (out_size >= T_DATA + kern_elems) ? 1 : 0;

    prep_kern<<<SUB_NO, 256>>>(W_conv, out + T_DATA, write_kern);

    group_gemm<<<(T_DATA + GM_ROWS - 1) / GM_ROWS, 256>>>(S_e, S_i, C_e, C_i);

    dim3 cgrid((T_DATA + CT - 1) / CT, SUB_NO);
    conv_mlp<<<cgrid, CTHREADS>>>(ff_w, ff_b, ff2_w, ff2_b, root_w);

    finalize<<<(T_DATA + 255) / 256, 256>>>(root_b, V_o, out);
}

// round 4
// speedup vs baseline: 1.2971x; 1.0169x over previous
#include <cuda_runtime.h>
#include <cstdint>

#define T_DATA 50000
#define E_NO   1000
#define I_NO   200
#define SUB_NO 20
#define H_NO   16
#define T_NO   200
#define COS_NO 20

// ---------------- persistent scratch (device globals; no allocation) --------
__device__ float g_Sg[2 * SUB_NO][T_DATA];                 // channel-major grouped signals (8 MB)
__device__ float g_kernT[SUB_NO][2][T_NO][H_NO];           // causal kernels, h-fastest (1 MB)
__device__ float g_partial[SUB_NO][T_DATA];                // per-subunit root partials (4 MB)

__device__ __forceinline__ float lrelu(float x) {
    return x >= 0.0f ? x : 0.01f * x;
}

// ---------------- packed f32x2 helpers (Blackwell) -------------------------
__device__ __forceinline__ unsigned long long f32x2_fma(
    unsigned long long a, unsigned long long b, unsigned long long c)
{
    unsigned long long d;
    asm("fma.rn.f32x2 %0, %1, %2, %3;" : "=l"(d) : "l"(a), "l"(b), "l"(c));
    return d;
}
__device__ __forceinline__ unsigned long long f32x2_bcast(float x)
{
    unsigned long long r;
    asm("mov.b64 %0, {%1, %1};" : "=l"(r) : "f"(x));
    return r;
}
__device__ __forceinline__ unsigned long long f32x2_pack(float lo, float hi)
{
    unsigned long long r;
    asm("mov.b64 %0, {%1, %2};" : "=l"(r) : "f"(lo), "f"(hi));
    return r;
}
__device__ __forceinline__ void f32x2_unpack(unsigned long long v, float& lo, float& hi)
{
    asm("mov.b64 {%0, %1}, %2;" : "=f"(lo), "=f"(hi) : "l"(v));
}

// ---------------------------------------------------------------------------
// Kernel 1: build raised-cosine basis, synthesize temporal kernels.
// ---------------------------------------------------------------------------
__global__ void prep_kern(const float* __restrict__ W_conv,
                          float* __restrict__ out_kern, int write_out)
{
    __shared__ float basis[COS_NO][T_NO];
    const int s = blockIdx.x;
    const float PI = 3.14159265358979323846f;

    for (int idx = threadIdx.x; idx < COS_NO * T_NO; idx += blockDim.x) {
        int b = idx / T_NO, t = idx % T_NO;
        float phi = 1.5707963267948966f * (float)b;
        float raw = 5.0f * logf((float)t + 1.0f);
        float v = 0.5f * cosf(raw - phi) + 0.5f;
        basis[b][t] = (raw >= phi - PI && raw <= phi + PI) ? v : 0.0f;
    }
    __syncthreads();

    for (int idx = threadIdx.x; idx < H_NO * 2 * T_NO; idx += blockDim.x) {
        int h = idx / (2 * T_NO);
        int c = (idx / T_NO) & 1;
        int k = idx % T_NO;
        int o = s * H_NO + h;
        const float* w = W_conv + (o * 2 + c) * COS_NO;
        float acc = 0.0f;
#pragma unroll
        for (int b = 0; b < COS_NO; b++) acc = fmaf(w[b], basis[b][k], acc);
        g_kernT[s][c][k][h] = acc;
        if (write_out)
            out_kern[(o * 2 + c) * T_NO + (T_NO - 1 - k)] = acc;
    }
}

// ---------------------------------------------------------------------------
// Kernel 2: synapse grouping GEMM, inner product in packed f32x2.
//   g_Sg[2s  ][t] = sum_e S_e[t,e] * C_syn_e[s,e]
//   g_Sg[2s+1][t] = sum_i S_i[t,i] * C_syn_i[s,i]
// ---------------------------------------------------------------------------
#define GM_ROWS 128
#define GM_KC   40
#define GM_PAD  44   // 11 x 16B row stride: odd -> conflict-free LDS.128

__global__ __launch_bounds__(256) void group_gemm(
    const float* __restrict__ S_e, const float* __restrict__ S_i,
    const float* __restrict__ Ce,  const float* __restrict__ Ci)
{
    __shared__ float sS[GM_ROWS][GM_PAD];
    __shared__ float sC[SUB_NO][GM_PAD];

    const int t0 = blockIdx.x * GM_ROWS;
    const int tid = threadIdx.x;
    const int w = tid >> 5, lane = tid & 31;
    const int cg = w >> 1;           // column group 0..3 -> cols [5*cg, 5*cg+5)
    const int rh = w & 1;
    const int r0 = rh * 64 + lane;   // rows r0 and r0+32

    for (int ph = 0; ph < 2; ph++) {
        const float* S = ph ? S_i : S_e;
        const float* C = ph ? Ci : Ce;
        const int K = ph ? I_NO : E_NO;

        unsigned long long acc0[5], acc1[5];
#pragma unroll
        for (int j = 0; j < 5; j++) { acc0[j] = 0ULL; acc1[j] = 0ULL; }

        for (int kc = 0; kc < K; kc += GM_KC) {
            // load 128 x 40 S tile (each thread: 5 float4)
            {
                int r = tid >> 1, half = tid & 1;
                int row = t0 + r;
#pragma unroll
                for (int j = 0; j < 5; j++) {
                    int col = kc + half * 20 + j * 4;
                    float4 v = make_float4(0.f, 0.f, 0.f, 0.f);
                    if (row < T_DATA)
                        v = *(const float4*)&S[(size_t)row * K + col];
                    *(float4*)&sS[r][half * 20 + j * 4] = v;
                }
            }
            // load 20 x 40 C tile
            if (tid < 200) {
                int col = tid / 10, seg = tid % 10;
                *(float4*)&sC[col][seg * 4] =
                    *(const float4*)&C[col * K + kc + seg * 4];
            }
            __syncthreads();

#pragma unroll
            for (int k4 = 0; k4 < GM_KC; k4 += 4) {
                float4 a0 = *(float4*)&sS[r0][k4];
                float4 a1 = *(float4*)&sS[r0 + 32][k4];
                unsigned long long a0lo = f32x2_pack(a0.x, a0.y);
                unsigned long long a0hi = f32x2_pack(a0.z, a0.w);
                unsigned long long a1lo = f32x2_pack(a1.x, a1.y);
                unsigned long long a1hi = f32x2_pack(a1.z, a1.w);
#pragma unroll
                for (int j = 0; j < 5; j++) {
                    float4 b = *(float4*)&sC[cg * 5 + j][k4];
                    unsigned long long blo = f32x2_pack(b.x, b.y);
                    unsigned long long bhi = f32x2_pack(b.z, b.w);
                    acc0[j] = f32x2_fma(a0lo, blo, acc0[j]);
                    acc0[j] = f32x2_fma(a0hi, bhi, acc0[j]);
                    acc1[j] = f32x2_fma(a1lo, blo, acc1[j]);
                    acc1[j] = f32x2_fma(a1hi, bhi, acc1[j]);
                }
            }
            __syncthreads();
        }
#pragma unroll
        for (int j = 0; j < 5; j++) {
            int ch = 2 * (cg * 5 + j) + ph;
            float lo, hi;
            if (t0 + r0 < T_DATA) {
                f32x2_unpack(acc0[j], lo, hi);
                g_Sg[ch][t0 + r0] = lo + hi;
            }
            if (t0 + r0 + 32 < T_DATA) {
                f32x2_unpack(acc1[j], lo, hi);
                g_Sg[ch][t0 + r0 + 32] = lo + hi;
            }
        }
    }
}

// ---------------------------------------------------------------------------
// Kernel 3: fused causal conv + MLP, inner loops in packed f32x2.
// ---------------------------------------------------------------------------
#define CT       512
#define CTHREADS 128

__global__ __launch_bounds__(CTHREADS) void conv_mlp(
    const float* __restrict__ ff_w,  const float* __restrict__ ff_b,
    const float* __restrict__ ff2_w, const float* __restrict__ ff2_b,
    const float* __restrict__ root_w)
{
    __shared__ float kern[2][T_NO][H_NO];          // 25.6 KB, h-fastest
    __shared__ float win[2][CT + T_NO];
    __shared__ float W1[H_NO][H_NO], W2[H_NO][H_NO];
    __shared__ float B1[H_NO], B2[H_NO], RW[H_NO];

    const int s  = blockIdx.y;
    const int t0 = blockIdx.x * CT;
    const int tid = threadIdx.x;

    {
        const float4* src = (const float4*)&g_kernT[s][0][0][0];
        float4* dst = (float4*)&kern[0][0][0];
        for (int i = tid; i < (2 * T_NO * H_NO) / 4; i += CTHREADS)
            dst[i] = src[i];
    }
    for (int c = 0; c < 2; c++) {
        const float* src = g_Sg[2 * s + c];
        for (int j = tid; j < CT + T_NO - 1; j += CTHREADS) {
            int t = t0 + j - (T_NO - 1);
            win[c][j] = (t >= 0 && t < T_DATA) ? src[t] : 0.0f;
        }
    }
    for (int i = tid; i < H_NO * H_NO; i += CTHREADS) {
        W1[i >> 4][i & 15] = ff_w[s * H_NO * H_NO + i];
        W2[i >> 4][i & 15] = ff2_w[s * H_NO * H_NO + i];
    }
    if (tid < H_NO) {
        B1[tid] = ff_b[s * H_NO + tid];
        B2[tid] = ff2_b[s * H_NO + tid];
        RW[tid] = root_w[s * H_NO + tid];
    }
    __syncthreads();

    // packed accumulators: acc2[q][p] = {acc[q][2p], acc[q][2p+1]}
    unsigned long long acc2[4][8];
#pragma unroll
    for (int q = 0; q < 4; q++)
#pragma unroll
        for (int p = 0; p < 8; p++) acc2[q][p] = 0ULL;

    for (int c = 0; c < 2; c++) {
        const float* wp = &win[c][tid + (T_NO - 1)];
        const ulonglong2* kp = (const ulonglong2*)&kern[c][0][0];
#pragma unroll 4
        for (int k = 0; k < T_NO; k++) {
            ulonglong2 ka  = kp[k * 4 + 0];   // h0..3
            ulonglong2 kb  = kp[k * 4 + 1];   // h4..7
            ulonglong2 kc2 = kp[k * 4 + 2];   // h8..11
            ulonglong2 kd  = kp[k * 4 + 3];   // h12..15
            float sv[4];
#pragma unroll
            for (int q = 0; q < 4; q++) sv[q] = wp[q * CTHREADS - k];
#pragma unroll
            for (int q = 0; q < 4; q++) {
                unsigned long long vv = f32x2_bcast(sv[q]);
                acc2[q][0] = f32x2_fma(vv, ka.x,  acc2[q][0]);
                acc2[q][1] = f32x2_fma(vv, ka.y,  acc2[q][1]);
                acc2[q][2] = f32x2_fma(vv, kb.x,  acc2[q][2]);
                acc2[q][3] = f32x2_fma(vv, kb.y,  acc2[q][3]);
                acc2[q][4] = f32x2_fma(vv, kc2.x, acc2[q][4]);
                acc2[q][5] = f32x2_fma(vv, kc2.y, acc2[q][5]);
                acc2[q][6] = f32x2_fma(vv, kd.x,  acc2[q][6]);
                acc2[q][7] = f32x2_fma(vv, kd.y,  acc2[q][7]);
            }
        }
    }

    // MLP + root partial; layer dots in packed f32x2 (8 packs over i).
#pragma unroll
    for (int q = 0; q < 4; q++) {
        int t = t0 + tid + q * CTHREADS;
        float x[H_NO], h1[H_NO];
#pragma unroll
        for (int p = 0; p < 8; p++) {
            float lo, hi;
            f32x2_unpack(acc2[q][p], lo, hi);
            x[2 * p]     = lrelu(lo);
            x[2 * p + 1] = lrelu(hi);
        }
        unsigned long long xp[8];
#pragma unroll
        for (int p = 0; p < 8; p++) xp[p] = f32x2_pack(x[2 * p], x[2 * p + 1]);

#pragma unroll
        for (int o = 0; o < H_NO; o++) {
            const ulonglong2* wrow = (const ulonglong2*)&W1[o][0];
            ulonglong2 w0 = wrow[0], w1 = wrow[1], w2 = wrow[2], w3 = wrow[3];
            unsigned long long a2 = f32x2_fma(xp[0], w0.x, 0ULL);
            a2 = f32x2_fma(xp[1], w0.y, a2);
            a2 = f32x2_fma(xp[2], w1.x, a2);
            a2 = f32x2_fma(xp[3], w1.y, a2);
            a2 = f32x2_fma(xp[4], w2.x, a2);
            a2 = f32x2_fma(xp[5], w2.y, a2);
            a2 = f32x2_fma(xp[6], w3.x, a2);
            a2 = f32x2_fma(xp[7], w3.y, a2);
            float lo, hi;
            f32x2_unpack(a2, lo, hi);
            h1[o] = lrelu(B1[o] + lo + hi);
        }
        unsigned long long hp[8];
#pragma unroll
        for (int p = 0; p < 8; p++) hp[p] = f32x2_pack(h1[2 * p], h1[2 * p + 1]);

        float pacc = 0.0f;
#pragma unroll
        for (int o = 0; o < H_NO; o++) {
            const ulonglong2* wrow = (const ulonglong2*)&W2[o][0];
            ulonglong2 w0 = wrow[0], w1 = wrow[1], w2 = wrow[2], w3 = wrow[3];
            unsigned long long a2 = f32x2_fma(hp[0], w0.x, 0ULL);
            a2 = f32x2_fma(hp[1], w0.y, a2);
            a2 = f32x2_fma(hp[2], w1.x, a2);
            a2 = f32x2_fma(hp[3], w1.y, a2);
            a2 = f32x2_fma(hp[4], w2.x, a2);
            a2 = f32x2_fma(hp[5], w2.y, a2);
            a2 = f32x2_fma(hp[6], w3.x, a2);
            a2 = f32x2_fma(hp[7], w3.y, a2);
            float lo, hi;
            f32x2_unpack(a2, lo, hi);
            pacc = fmaf(lrelu(B2[o] + lo + hi), RW[o], pacc);
        }
        if (t < T_DATA) g_partial[s][t] = pacc;
    }
}

// ---------------------------------------------------------------------------
// Kernel 4: V[t] = sum_s partial[s][t] + root_b + V_o
// ---------------------------------------------------------------------------
__global__ void finalize(const float* __restrict__ root_b,
                         const float* __restrict__ V_o,
                         float* __restrict__ out)
{
    int t = blockIdx.x * 256 + threadIdx.x;
    if (t >= T_DATA) return;
    float sum = root_b[0] + V_o[0];
#pragma unroll
    for (int s = 0; s < SUB_NO; s++) sum += g_partial[s][t];
    out[t] = sum;
}

// ---------------------------------------------------------------------------
extern "C" void kernel_launch(void* const* d_in, const int* in_sizes, int n_in,
                              void* d_out, int out_size)
{
    const float* S_e    = (const float*)d_in[0];
    const float* S_i    = (const float*)d_in[1];
    const float* C_e    = (const float*)d_in[2];
    const float* C_i    = (const float*)d_in[3];
    const float* W_conv = (const float*)d_in[4];
    const float* ff_w   = (const float*)d_in[5];
    const float* ff_b   = (const float*)d_in[6];
    const float* ff2_w  = (const float*)d_in[7];
    const float* ff2_b  = (const float*)d_in[8];
    const float* root_w = (const float*)d_in[9];
    const float* root_b = (const float*)d_in[10];
    const float* V_o    = (const float*)d_in[11];
    (void)in_sizes; (void)n_in;

    float* out = (float*)d_out;
    const int kern_elems = SUB_NO * H_NO * 2 * T_NO;
    int write_kern = (out_size >= T_DATA + kern_elems) ? 1 : 0;

    prep_kern<<<SUB_NO, 256>>>(W_conv, out + T_DATA, write_kern);

    group_gemm<<<(T_DATA + GM_ROWS - 1) / GM_ROWS, 256>>>(S_e, S_i, C_e, C_i);

    dim3 cgrid((T_DATA + CT - 1) / CT, SUB_NO);
    conv_mlp<<<cgrid, CTHREADS>>>(ff_w, ff_b, ff2_w, ff2_b, root_w);

    finalize<<<(T_DATA + 255) / 256, 256>>>(root_b, V_o, out);
}